// round 1
// baseline (speedup 1.0000x reference)
#include <cuda_runtime.h>
#include <cuda_bf16.h>
#include <cstdint>

#define VOCAB 500000
#define DIM 128
#define RANK 8
#define SCALING 2.0f
#define RANK_THRESHOLD 0.1f

// Flag: 1 if index tensor is int64, 0 if int32. Set by detector kernel each call
// (deterministic: same input -> same flag).
__device__ int g_idx_is_i64;

__global__ void detect_idx_dtype(const long long* __restrict__ x64, int nsamp) {
    if (threadIdx.x == 0 && blockIdx.x == 0) {
        int ok = 1;
        for (int i = 0; i < nsamp; i++) {
            long long v = x64[i];
            if (v < 0 || v >= (long long)VOCAB) { ok = 0; break; }
        }
        g_idx_is_i64 = ok;
    }
}

__global__ void __launch_bounds__(256)
cora_embed_kernel(const void* __restrict__ xv,
                  const float* __restrict__ E,     // [VOCAB, 128]
                  const float* __restrict__ A,     // [8, 128]
                  const float* __restrict__ Bm,    // [VOCAB, 8]
                  const float* __restrict__ rp,    // [8]
                  float* __restrict__ out,         // [ntok, 128]
                  int ntok)
{
    const int lane = threadIdx.x & 31;
    const int warp_global = (blockIdx.x * blockDim.x + threadIdx.x) >> 5;
    const int nwarps = (gridDim.x * blockDim.x) >> 5;

    // Build effective (scaled+gated) A columns for this lane's 4 output dims.
    // a[r] = SCALING * gate(r) * A[r, lane*4 .. lane*4+3]
    float4 a[RANK];
#pragma unroll
    for (int r = 0; r < RANK; r++) {
        float g = (rp[r] > RANK_THRESHOLD) ? SCALING : 0.0f;
        float4 av = reinterpret_cast<const float4*>(A)[r * (DIM / 4) + lane];
        a[r].x = av.x * g; a[r].y = av.y * g; a[r].z = av.z * g; a[r].w = av.w * g;
    }

    const bool is64 = (g_idx_is_i64 != 0);
    const long long* x64 = reinterpret_cast<const long long*>(xv);
    const int*       x32 = reinterpret_cast<const int*>(xv);

    for (int t = warp_global; t < ntok; t += nwarps) {
        long long idx = is64 ? x64[t] : (long long)x32[t];

        const float4* erow = reinterpret_cast<const float4*>(E + idx * DIM);
        float4 o = __ldg(&erow[lane]);

        // B row: 8 floats, same 32B for the whole warp -> broadcast from L1.
        const float4* brow = reinterpret_cast<const float4*>(Bm + idx * RANK);
        float4 b0 = __ldg(&brow[0]);
        float4 b1 = __ldg(&brow[1]);

        o.x = fmaf(b0.x, a[0].x, o.x); o.y = fmaf(b0.x, a[0].y, o.y);
        o.z = fmaf(b0.x, a[0].z, o.z); o.w = fmaf(b0.x, a[0].w, o.w);
        o.x = fmaf(b0.y, a[1].x, o.x); o.y = fmaf(b0.y, a[1].y, o.y);
        o.z = fmaf(b0.y, a[1].z, o.z); o.w = fmaf(b0.y, a[1].w, o.w);
        o.x = fmaf(b0.z, a[2].x, o.x); o.y = fmaf(b0.z, a[2].y, o.y);
        o.z = fmaf(b0.z, a[2].z, o.z); o.w = fmaf(b0.z, a[2].w, o.w);
        o.x = fmaf(b0.w, a[3].x, o.x); o.y = fmaf(b0.w, a[3].y, o.y);
        o.z = fmaf(b0.w, a[3].z, o.z); o.w = fmaf(b0.w, a[3].w, o.w);
        o.x = fmaf(b1.x, a[4].x, o.x); o.y = fmaf(b1.x, a[4].y, o.y);
        o.z = fmaf(b1.x, a[4].z, o.z); o.w = fmaf(b1.x, a[4].w, o.w);
        o.x = fmaf(b1.y, a[5].x, o.x); o.y = fmaf(b1.y, a[5].y, o.y);
        o.z = fmaf(b1.y, a[5].z, o.z); o.w = fmaf(b1.y, a[5].w, o.w);
        o.x = fmaf(b1.z, a[6].x, o.x); o.y = fmaf(b1.z, a[6].y, o.y);
        o.z = fmaf(b1.z, a[6].z, o.z); o.w = fmaf(b1.z, a[6].w, o.w);
        o.x = fmaf(b1.w, a[7].x, o.x); o.y = fmaf(b1.w, a[7].y, o.y);
        o.z = fmaf(b1.w, a[7].z, o.z); o.w = fmaf(b1.w, a[7].w, o.w);

        reinterpret_cast<float4*>(out + (long long)t * DIM)[lane] = o;
    }
}

extern "C" void kernel_launch(void* const* d_in, const int* in_sizes, int n_in,
                              void* d_out, int out_size)
{
    const void*  x  = d_in[0];                          // [B, L] int32 or int64
    const float* E  = (const float*)d_in[1];            // [VOCAB, 128]
    const float* A  = (const float*)d_in[2];            // [8, 128]
    const float* Bm = (const float*)d_in[3];            // [VOCAB, 8]
    const float* rp = (const float*)d_in[4];            // [8]
    float* out = (float*)d_out;

    const int ntok = out_size / DIM;                    // robust vs index dtype ambiguity

    detect_idx_dtype<<<1, 32>>>((const long long*)x, 64);

    const int threads = 256;
    const int warps_per_block = threads / 32;
    int blocks = (ntok + warps_per_block - 1) / warps_per_block;
    cora_embed_kernel<<<blocks, threads>>>(x, E, A, Bm, rp, out, ntok);
}

// round 2
// speedup vs baseline: 1.6951x; 1.6951x over previous
#include <cuda_runtime.h>
#include <cuda_bf16.h>
#include <cstdint>

#define VOCAB 500000
#define DIM 128
#define RANK 8
#define SCALING 2.0f
#define RANK_THRESHOLD 0.1f
#define TPW 4   // tokens per warp

// Flag: 1 if index tensor is int64, 0 if int32. Set deterministically each call.
__device__ int g_idx_is_i64;

__global__ void detect_idx_dtype(const long long* __restrict__ x64, int nsamp) {
    if (threadIdx.x == 0 && blockIdx.x == 0) {
        int ok = 1;
        for (int i = 0; i < nsamp; i++) {
            long long v = x64[i];
            if (v < 0 || v >= (long long)VOCAB) { ok = 0; break; }
        }
        g_idx_is_i64 = ok;
    }
}

__global__ void __launch_bounds__(256)
cora_embed_kernel(const void* __restrict__ xv,
                  const float* __restrict__ E,     // [VOCAB, 128]
                  const float* __restrict__ A,     // [8, 128]
                  const float* __restrict__ Bm,    // [VOCAB, 8]
                  const float* __restrict__ rp,    // [8]
                  float* __restrict__ out,         // [ntok, 128]
                  int ntok)
{
    const int lane = threadIdx.x & 31;
    const int warp_global = (blockIdx.x * blockDim.x + threadIdx.x) >> 5;

    // Gated+scaled A columns for this lane's 4 output dims (32 regs, reused all tokens).
    float4 a[RANK];
#pragma unroll
    for (int r = 0; r < RANK; r++) {
        float g = (rp[r] > RANK_THRESHOLD) ? SCALING : 0.0f;
        float4 av = reinterpret_cast<const float4*>(A)[r * (DIM / 4) + lane];
        a[r].x = av.x * g; a[r].y = av.y * g; a[r].z = av.z * g; a[r].w = av.w * g;
    }

    const bool is64 = (g_idx_is_i64 != 0);
    const long long* x64 = reinterpret_cast<const long long*>(xv);
    const int*       x32 = reinterpret_cast<const int*>(xv);

    const int base = warp_global * TPW;
    if (base >= ntok) return;
    const int cnt = min(TPW, ntok - base);

    if (cnt == TPW) {
        // ---- fast path: fully batched loads (MLP = 4 E-rows + 8 B-vecs in flight) ----
        long long idx[TPW];
#pragma unroll
        for (int i = 0; i < TPW; i++)
            idx[i] = is64 ? x64[base + i] : (long long)x32[base + i];

        float4 e[TPW], b0[TPW], b1[TPW];
#pragma unroll
        for (int i = 0; i < TPW; i++) {
            const float4* erow = reinterpret_cast<const float4*>(E + idx[i] * DIM);
            e[i] = __ldg(&erow[lane]);
            const float4* brow = reinterpret_cast<const float4*>(Bm + idx[i] * RANK);
            b0[i] = __ldg(&brow[0]);
            b1[i] = __ldg(&brow[1]);
        }

#pragma unroll
        for (int i = 0; i < TPW; i++) {
            float4 o = e[i];
            o.x = fmaf(b0[i].x, a[0].x, o.x); o.y = fmaf(b0[i].x, a[0].y, o.y);
            o.z = fmaf(b0[i].x, a[0].z, o.z); o.w = fmaf(b0[i].x, a[0].w, o.w);
            o.x = fmaf(b0[i].y, a[1].x, o.x); o.y = fmaf(b0[i].y, a[1].y, o.y);
            o.z = fmaf(b0[i].y, a[1].z, o.z); o.w = fmaf(b0[i].y, a[1].w, o.w);
            o.x = fmaf(b0[i].z, a[2].x, o.x); o.y = fmaf(b0[i].z, a[2].y, o.y);
            o.z = fmaf(b0[i].z, a[2].z, o.z); o.w = fmaf(b0[i].z, a[2].w, o.w);
            o.x = fmaf(b0[i].w, a[3].x, o.x); o.y = fmaf(b0[i].w, a[3].y, o.y);
            o.z = fmaf(b0[i].w, a[3].z, o.z); o.w = fmaf(b0[i].w, a[3].w, o.w);
            o.x = fmaf(b1[i].x, a[4].x, o.x); o.y = fmaf(b1[i].x, a[4].y, o.y);
            o.z = fmaf(b1[i].x, a[4].z, o.z); o.w = fmaf(b1[i].x, a[4].w, o.w);
            o.x = fmaf(b1[i].y, a[5].x, o.x); o.y = fmaf(b1[i].y, a[5].y, o.y);
            o.z = fmaf(b1[i].y, a[5].z, o.z); o.w = fmaf(b1[i].y, a[5].w, o.w);
            o.x = fmaf(b1[i].z, a[6].x, o.x); o.y = fmaf(b1[i].z, a[6].y, o.y);
            o.z = fmaf(b1[i].z, a[6].z, o.z); o.w = fmaf(b1[i].z, a[6].w, o.w);
            o.x = fmaf(b1[i].w, a[7].x, o.x); o.y = fmaf(b1[i].w, a[7].y, o.y);
            o.z = fmaf(b1[i].w, a[7].z, o.z); o.w = fmaf(b1[i].w, a[7].w, o.w);
            // streaming store: write-once output must not evict E rows from L2
            __stcs(reinterpret_cast<float4*>(out + (long long)(base + i) * DIM) + lane, o);
        }
    } else {
        // ---- tail path ----
        for (int i = 0; i < cnt; i++) {
            long long idx = is64 ? x64[base + i] : (long long)x32[base + i];
            const float4* erow = reinterpret_cast<const float4*>(E + idx * DIM);
            float4 o = __ldg(&erow[lane]);
            const float4* brow = reinterpret_cast<const float4*>(Bm + idx * RANK);
            float4 b0 = __ldg(&brow[0]);
            float4 b1 = __ldg(&brow[1]);
            o.x = fmaf(b0.x, a[0].x, o.x); o.y = fmaf(b0.x, a[0].y, o.y);
            o.z = fmaf(b0.x, a[0].z, o.z); o.w = fmaf(b0.x, a[0].w, o.w);
            o.x = fmaf(b0.y, a[1].x, o.x); o.y = fmaf(b0.y, a[1].y, o.y);
            o.z = fmaf(b0.y, a[1].z, o.z); o.w = fmaf(b0.y, a[1].w, o.w);
            o.x = fmaf(b0.z, a[2].x, o.x); o.y = fmaf(b0.z, a[2].y, o.y);
            o.z = fmaf(b0.z, a[2].z, o.z); o.w = fmaf(b0.z, a[2].w, o.w);
            o.x = fmaf(b0.w, a[3].x, o.x); o.y = fmaf(b0.w, a[3].y, o.y);
            o.z = fmaf(b0.w, a[3].z, o.z); o.w = fmaf(b0.w, a[3].w, o.w);
            o.x = fmaf(b1.x, a[4].x, o.x); o.y = fmaf(b1.x, a[4].y, o.y);
            o.z = fmaf(b1.x, a[4].z, o.z); o.w = fmaf(b1.x, a[4].w, o.w);
            o.x = fmaf(b1.y, a[5].x, o.x); o.y = fmaf(b1.y, a[5].y, o.y);
            o.z = fmaf(b1.y, a[5].z, o.z); o.w = fmaf(b1.y, a[5].w, o.w);
            o.x = fmaf(b1.z, a[6].x, o.x); o.y = fmaf(b1.z, a[6].y, o.y);
            o.z = fmaf(b1.z, a[6].z, o.z); o.w = fmaf(b1.z, a[6].w, o.w);
            o.x = fmaf(b1.w, a[7].x, o.x); o.y = fmaf(b1.w, a[7].y, o.y);
            o.z = fmaf(b1.w, a[7].z, o.z); o.w = fmaf(b1.w, a[7].w, o.w);
            __stcs(reinterpret_cast<float4*>(out + (long long)(base + i) * DIM) + lane, o);
        }
    }
}

extern "C" void kernel_launch(void* const* d_in, const int* in_sizes, int n_in,
                              void* d_out, int out_size)
{
    const void*  x  = d_in[0];                          // [B, L] int32 or int64
    const float* E  = (const float*)d_in[1];            // [VOCAB, 128]
    const float* A  = (const float*)d_in[2];            // [8, 128]
    const float* Bm = (const float*)d_in[3];            // [VOCAB, 8]
    const float* rp = (const float*)d_in[4];            // [8]
    float* out = (float*)d_out;

    const int ntok = out_size / DIM;

    detect_idx_dtype<<<1, 32>>>((const long long*)x, 64);

    const int threads = 256;
    const int warps_per_block = threads / 32;
    const int tok_per_block = warps_per_block * TPW;
    int blocks = (ntok + tok_per_block - 1) / tok_per_block;
    cora_embed_kernel<<<blocks, threads>>>(x, E, A, Bm, rp, out, ntok);
}

// round 3
// speedup vs baseline: 2.3409x; 1.3810x over previous
#include <cuda_runtime.h>
#include <cuda_bf16.h>
#include <cstdint>

#define VOCAB 500000
#define DIM 128
#define RANK 8
#define SCALING 2.0f
#define RANK_THRESHOLD 0.1f

#define NWARPS 8          // warps per block (256 threads)
#define STAGES 8          // cp.async pipeline depth (tokens in flight per warp)
#define CHUNK 64          // tokens per warp

__device__ int g_idx_is_i64;

__global__ void detect_idx_dtype(const long long* __restrict__ x64, int nsamp) {
    if (threadIdx.x == 0 && blockIdx.x == 0) {
        int ok = 1;
        for (int i = 0; i < nsamp; i++) {
            long long v = x64[i];
            if (v < 0 || v >= (long long)VOCAB) { ok = 0; break; }
        }
        g_idx_is_i64 = ok;
    }
}

__device__ __forceinline__ void cp_async16(uint32_t smem_addr, const void* gptr) {
    asm volatile("cp.async.cg.shared.global [%0], [%1], 16;\n"
                 :: "r"(smem_addr), "l"(gptr));
}
__device__ __forceinline__ void cp_commit() {
    asm volatile("cp.async.commit_group;\n");
}
__device__ __forceinline__ void cp_wait_all_but(int){}  // placeholder (immediate needed)

__global__ void __launch_bounds__(NWARPS * 32)
cora_embed_kernel(const void* __restrict__ xv,
                  const float* __restrict__ E,     // [VOCAB, 128]
                  const float* __restrict__ A,     // [8, 128]
                  const float* __restrict__ Bm,    // [VOCAB, 8]
                  const float* __restrict__ rp,    // [8]
                  float* __restrict__ out,         // [ntok, 128]
                  int ntok)
{
    __shared__ float e_buf[NWARPS][STAGES][DIM];   // 32 KB
    __shared__ float b_buf[NWARPS][STAGES][RANK];  // 2 KB

    const int lane = threadIdx.x & 31;
    const int w    = threadIdx.x >> 5;
    const int warp_global = blockIdx.x * NWARPS + w;

    // Gated+scaled A columns for this lane's 4 output dims.
    float4 a[RANK];
#pragma unroll
    for (int r = 0; r < RANK; r++) {
        float g = (rp[r] > RANK_THRESHOLD) ? SCALING : 0.0f;
        float4 av = reinterpret_cast<const float4*>(A)[r * (DIM / 4) + lane];
        a[r].x = av.x * g; a[r].y = av.y * g; a[r].z = av.z * g; a[r].w = av.w * g;
    }

    const bool is64 = (g_idx_is_i64 != 0);
    const long long* x64 = reinterpret_cast<const long long*>(xv);
    const int*       x32 = reinterpret_cast<const int*>(xv);

    const int base = warp_global * CHUNK;
    if (base >= ntok) return;
    const int tend = min(base + CHUNK, ntok);
    const int nt = tend - base;

    const uint32_t e_base = (uint32_t)__cvta_generic_to_shared(&e_buf[w][0][0]);
    const uint32_t b_base = (uint32_t)__cvta_generic_to_shared(&b_buf[w][0][0]);

    // ---------------- prologue: fill pipeline ----------------
#pragma unroll
    for (int s = 0; s < STAGES; s++) {
        int t = base + s;
        if (t < tend) {
            long long idx = is64 ? x64[t] : (long long)x32[t];
            cp_async16(e_base + (uint32_t)(s * DIM + lane * 4) * 4,
                       E + idx * DIM + lane * 4);
            if (lane < 2)
                cp_async16(b_base + (uint32_t)(s * RANK + lane * 4) * 4,
                           Bm + idx * RANK + lane * 4);
        }
        cp_commit();
    }

    // ---------------- steady state ----------------
    for (int i = 0; i < nt; i++) {
        asm volatile("cp.async.wait_group %0;\n" :: "n"(STAGES - 1));
        __syncwarp();   // make lanes 0/1's B copies visible to all lanes

        const int s = i & (STAGES - 1);
        float4 e  = *reinterpret_cast<const float4*>(&e_buf[w][s][lane * 4]);
        float4 b0 = *reinterpret_cast<const float4*>(&b_buf[w][s][0]);
        float4 b1 = *reinterpret_cast<const float4*>(&b_buf[w][s][4]);

        __syncwarp();   // all lanes done reading stage s before it is refilled

        // refill stage s with token i+STAGES
        int t = base + i + STAGES;
        if (t < tend) {
            long long idx = is64 ? x64[t] : (long long)x32[t];
            cp_async16(e_base + (uint32_t)(s * DIM + lane * 4) * 4,
                       E + idx * DIM + lane * 4);
            if (lane < 2)
                cp_async16(b_base + (uint32_t)(s * RANK + lane * 4) * 4,
                           Bm + idx * RANK + lane * 4);
        }
        cp_commit();

        float4 o = e;
        o.x = fmaf(b0.x, a[0].x, o.x); o.y = fmaf(b0.x, a[0].y, o.y);
        o.z = fmaf(b0.x, a[0].z, o.z); o.w = fmaf(b0.x, a[0].w, o.w);
        o.x = fmaf(b0.y, a[1].x, o.x); o.y = fmaf(b0.y, a[1].y, o.y);
        o.z = fmaf(b0.y, a[1].z, o.z); o.w = fmaf(b0.y, a[1].w, o.w);
        o.x = fmaf(b0.z, a[2].x, o.x); o.y = fmaf(b0.z, a[2].y, o.y);
        o.z = fmaf(b0.z, a[2].z, o.z); o.w = fmaf(b0.z, a[2].w, o.w);
        o.x = fmaf(b0.w, a[3].x, o.x); o.y = fmaf(b0.w, a[3].y, o.y);
        o.z = fmaf(b0.w, a[3].z, o.z); o.w = fmaf(b0.w, a[3].w, o.w);
        o.x = fmaf(b1.x, a[4].x, o.x); o.y = fmaf(b1.x, a[4].y, o.y);
        o.z = fmaf(b1.x, a[4].z, o.z); o.w = fmaf(b1.x, a[4].w, o.w);
        o.x = fmaf(b1.y, a[5].x, o.x); o.y = fmaf(b1.y, a[5].y, o.y);
        o.z = fmaf(b1.y, a[5].z, o.z); o.w = fmaf(b1.y, a[5].w, o.w);
        o.x = fmaf(b1.z, a[6].x, o.x); o.y = fmaf(b1.z, a[6].y, o.y);
        o.z = fmaf(b1.z, a[6].z, o.z); o.w = fmaf(b1.z, a[6].w, o.w);
        o.x = fmaf(b1.w, a[7].x, o.x); o.y = fmaf(b1.w, a[7].y, o.y);
        o.z = fmaf(b1.w, a[7].z, o.z); o.w = fmaf(b1.w, a[7].w, o.w);

        __stcs(reinterpret_cast<float4*>(out + (long long)(base + i) * DIM) + lane, o);
    }
}

extern "C" void kernel_launch(void* const* d_in, const int* in_sizes, int n_in,
                              void* d_out, int out_size)
{
    const void*  x  = d_in[0];                // [B, L] int32 or int64
    const float* E  = (const float*)d_in[1];  // [VOCAB, 128]
    const float* A  = (const float*)d_in[2];  // [8, 128]
    const float* Bm = (const float*)d_in[3];  // [VOCAB, 8]
    const float* rp = (const float*)d_in[4];  // [8]
    float* out = (float*)d_out;

    const int ntok = out_size / DIM;

    detect_idx_dtype<<<1, 32>>>((const long long*)x, 64);

    const int tok_per_block = NWARPS * CHUNK;
    int blocks = (ntok + tok_per_block - 1) / tok_per_block;
    cora_embed_kernel<<<blocks, NWARPS * 32>>>(x, E, A, Bm, rp, out, ntok);
}